// round 13
// baseline (speedup 1.0000x reference)
#include <cuda_runtime.h>
#include <math_constants.h>

#define B      64
#define C      2048
#define FM     14
#define NPIX   196
#define NCHUNK 16
#define CCHUNK 128   // C / NCHUNK
#define TW     837

// scratch (no cudaMalloc allowed); zero-initialized at module load
__device__ float    g_partial[NCHUNK * B * NPIX];
__device__ unsigned g_cnt[B];    // k1 chunk arrivals per batch
__device__ unsigned g_done[B];   // k2 group-block consumptions per batch

__constant__ int d_RH[11]   = {4,3,5,6,5,7,8,6,10,7,9};
__constant__ int d_RW[11]   = {4,5,3,6,7,5,8,10,6,9,7};
__constant__ int d_WOFF[12] = {0,121,241,361,442,522,602,651,696,741,789,837};
__constant__ int d_GR0[3]   = {0, 3, 6};
__constant__ int d_GOFF[3]  = {0, 361, 602};
__constant__ int d_GW[3]    = {361, 241, 235};
__constant__ int d_GN[3]    = {3, 2, 1};
__constant__ int d_GSLOT[3] = {0, 3, 5};

// ---------------------------------------------------------------------------
// Kernel 1: channel-chunk reduction.  grid = (NCHUNK, B), block = 196.
// ~8 TB/s — at HBM cap.  PDL trigger at block END (R11 timing): k2 schedules
// only as k1 drains.  Per-batch completion via fence + g_cnt (release).
// ---------------------------------------------------------------------------
__global__ void __launch_bounds__(196) appm_reduce_kernel(const float* __restrict__ x)
{
    const int chunk = blockIdx.x;
    const int b     = blockIdx.y;
    const int t     = threadIdx.x;
    const int q     = t % 49;
    const int cw    = t / 49;

    const float4* base = reinterpret_cast<const float4*>(x)
                       + ((size_t)b * C + (size_t)chunk * CCHUNK) * 49;

    float4 acc = make_float4(0.f, 0.f, 0.f, 0.f);
#pragma unroll 8
    for (int c = cw; c < CCHUNK; c += 4) {
        float4 v = __ldcs(base + (size_t)c * 49 + q);
        acc.x += v.x; acc.y += v.y; acc.z += v.z; acc.w += v.w;
    }

    __shared__ float s[NPIX];
    if (t < NPIX) s[t] = 0.f;
    __syncthreads();
    atomicAdd(&s[q * 4 + 0], acc.x);
    atomicAdd(&s[q * 4 + 1], acc.y);
    atomicAdd(&s[q * 4 + 2], acc.z);
    atomicAdd(&s[q * 4 + 3], acc.w);
    __syncthreads();
    if (t < NPIX)
        g_partial[(chunk * B + b) * NPIX + t] = s[t];
    __syncthreads();                             // all partial stores issued
    if (t == 0) {
        __threadfence();                         // release
        atomicAdd(&g_cnt[b], 1u);
    }
    cudaTriggerProgrammaticLaunchCompletion();   // k2 may schedule (tail)
}

// ---------------------------------------------------------------------------
// Kernel 2: per-(batch, group) scores + greedy NMS.  grid = (B, 3), block 256.
// PDL-launched at k1 tail; waits ONLY on its own batch's 16 chunks, skipping
// k1's last-wave drain spread.  3rd group-block per batch resets counters.
// Output layout (fp32): [B*6 indices][B*6 scores][B*837 all_scores]
// ---------------------------------------------------------------------------
__global__ void __launch_bounds__(256) appm_nms_kernel(float* __restrict__ out)
{
    const int b   = blockIdx.x;
    const int g   = blockIdx.y;
    const int tid = threadIdx.x;
    const int lane = tid & 31;
    const int wid  = tid >> 5;

    const int goff  = d_GOFF[g];
    const int W     = d_GW[g];
    const int nsel  = d_GN[g];
    const int slot0 = d_GSLOT[g];
    const int r0    = d_GR0[g];

    __shared__ float  y[NPIX];
    __shared__ float  SAT[FM + 1][FM + 1];
    __shared__ float  sc[361];
    __shared__ float  cx0[361], cy0[361], cx1[361], cy1[361];
    __shared__ int    wmeta[361];                 // i | j<<8 | rh<<16 | rw<<24
    __shared__ unsigned char valid[361];
    __shared__ float  warp_s[8];
    __shared__ int    warp_i[8];

    // ======= data-independent prologue (overlaps k1 tail via PDL) =======
    if (tid < FM + 1) { SAT[0][tid] = 0.f; SAT[tid][0] = 0.f; }
    for (int w = tid; w < W; w += 256) {
        const int gw = goff + w;
        int r = r0;
        while (gw >= d_WOFF[r + 1]) r++;
        const int loc = gw - d_WOFF[r];
        const int rh  = d_RH[r], rw = d_RW[r];
        const int nw  = FM - rw + 1;
        const int i   = loc / nw, j = loc % nw;
        wmeta[w] = i | (j << 8) | (rh << 16) | (rw << 24);
        cx0[w] = (float)(j * 32);
        cy0[w] = (float)(i * 32);
        cx1[w] = (float)((j + rw) * 32 - 1);
        cy1[w] = (float)((i + rh) * 32 - 1);
        valid[w] = 1;
    }

    // ======= per-batch wait: only THIS batch's 16 chunks =======
    if (tid == 0) {
        while (atomicAdd(&g_cnt[b], 0u) < NCHUNK) __nanosleep(64);
        __threadfence();                          // acquire
    }
    __syncthreads();

    // ======= data-dependent phase =======
    if (tid < NPIX) {
        float acc = 0.f;
#pragma unroll
        for (int ch = 0; ch < NCHUNK; ch++)
            acc += g_partial[(ch * B + b) * NPIX + tid];
        y[tid] = acc;
    }
    __syncthreads();                              // partials consumed

    // reset counters for graph-replay determinism (3rd block of this batch)
    if (tid == 0) {
        const unsigned d = atomicAdd(&g_done[b], 1u);
        if (d == 2u) { g_cnt[b] = 0u; g_done[b] = 0u; __threadfence(); }
    }

    // integral image in float (matches ref to ~2.5e-7)
    if (tid < FM) {
        float r = 0.f;
#pragma unroll
        for (int j = 0; j < FM; j++) {
            r += y[tid * FM + j];
            SAT[tid + 1][j + 1] = r;
        }
    }
    __syncthreads();
    if (tid < FM) {
        float r = 0.f;
#pragma unroll
        for (int i = 1; i <= FM; i++) {
            r += SAT[i][tid + 1];
            SAT[i][tid + 1] = r;
        }
    }
    __syncthreads();

    // window scores from packed meta
    for (int w = tid; w < W; w += 256) {
        const int m  = wmeta[w];
        const int i  = m & 255, j = (m >> 8) & 255;
        const int rh = (m >> 16) & 255, rw = (m >> 24) & 255;
        const float s = SAT[i + rh][j + rw] - SAT[i][j + rw]
                      - SAT[i + rh][j]      + SAT[i][j];
        const float sv = s / (float)(rh * rw);
        sc[w] = sv;
        out[2 * B * 6 + (size_t)b * TW + goff + w] = sv;   // all_scores
    }
    __syncthreads();

    // ---- greedy NMS: 2 barriers/step (all threads fold the 8 warp winners) ----
    int last = 0;
    for (int step = 0; step < nsel; step++) {
        float bs = -CUDART_INF_F;
        int   bi = 0x7fffffff;
        for (int w = tid; w < W; w += 256) {
            if (valid[w]) {
                const float s = sc[w];
                if (s > bs) { bs = s; bi = w; }   // first max kept = jnp.argmax
            }
        }
#pragma unroll
        for (int o = 16; o > 0; o >>= 1) {
            const float s2 = __shfl_down_sync(0xffffffffu, bs, o);
            const int   i2 = __shfl_down_sync(0xffffffffu, bi, o);
            if (s2 > bs || (s2 == bs && i2 < bi)) { bs = s2; bi = i2; }
        }
        if (lane == 0) { warp_s[wid] = bs; warp_i[wid] = bi; }
        __syncthreads();
        // every thread folds the 8 winners identically (no tid0 round-trip)
        float fs = warp_s[0]; int fi = warp_i[0];
#pragma unroll
        for (int k = 1; k < 8; k++) {
            const float s2 = warp_s[k]; const int i2 = warp_i[k];
            if (s2 > fs || (s2 == fs && i2 < fi)) { fs = s2; fi = i2; }
        }
        const bool anyv = fs > -CUDART_INF_F;
        const int  idx  = anyv ? fi : last;       // fallback: repeat last

        if (tid == 0)
            out[(size_t)b * 6 + slot0 + step] = (float)(goff + idx);
        if (tid == 1)
            out[B * 6 + (size_t)b * 6 + slot0 + step] = sc[idx];

        if (anyv) {
            const float sx0 = cx0[idx], sy0 = cy0[idx];
            const float sx1 = cx1[idx], sy1 = cy1[idx];
            const float sarea = (sx1 - sx0 + 1.f) * (sy1 - sy0 + 1.f);
            for (int w = tid; w < W; w += 256) {
                const float lx = fmaxf(cx0[w], sx0);
                const float ly = fmaxf(cy0[w], sy0);
                const float rx = fminf(cx1[w], sx1);
                const float ry = fminf(cy1[w], sy1);
                const float wx = rx - lx + 1.f;
                const float wy = ry - ly + 1.f;
                const float inter = (wx < 0.f || wy < 0.f) ? 0.f : wx * wy;
                const float area  = (cx1[w] - cx0[w] + 1.f) * (cy1[w] - cy0[w] + 1.f);
                const float iou   = inter / (area + sarea - inter);
                if (iou > 0.25f) valid[w] = 0;    // self-IoU=1 clears sel
            }
            if (tid == 0) valid[idx] = 0;
        }
        last = idx;
        __syncthreads();
    }
}

extern "C" void kernel_launch(void* const* d_in, const int* in_sizes, int n_in,
                              void* d_out, int out_size)
{
    const float* x = (const float*)d_in[0];
    float* out = (float*)d_out;

    appm_reduce_kernel<<<dim3(NCHUNK, B), 196>>>(x);

    cudaLaunchConfig_t cfg = {};
    cfg.gridDim  = dim3(B, 3);
    cfg.blockDim = dim3(256);
    cudaLaunchAttribute attrs[1];
    attrs[0].id = cudaLaunchAttributeProgrammaticStreamSerialization;
    attrs[0].val.programmaticStreamSerializationAllowed = 1;
    cfg.attrs    = attrs;
    cfg.numAttrs = 1;
    cudaLaunchKernelEx(&cfg, appm_nms_kernel, out);
}

// round 14
// speedup vs baseline: 1.0088x; 1.0088x over previous
#include <cuda_runtime.h>
#include <math_constants.h>

#define B      64
#define C      2048
#define FM     14
#define NPIX   196
#define NCHUNK 16
#define CCHUNK 128   // C / NCHUNK
#define TW     837

// scratch for per-chunk partial channel sums (no cudaMalloc allowed)
__device__ float g_partial[NCHUNK * B * NPIX];

__constant__ int d_RH[11]   = {4,3,5,6,5,7,8,6,10,7,9};
__constant__ int d_RW[11]   = {4,5,3,6,7,5,8,10,6,9,7};
__constant__ int d_WOFF[12] = {0,121,241,361,442,522,602,651,696,741,789,837};
__constant__ int d_GR0[3]   = {0, 3, 6};
__constant__ int d_GOFF[3]  = {0, 361, 602};
__constant__ int d_GW[3]    = {361, 241, 235};
__constant__ int d_GN[3]    = {3, 2, 1};
__constant__ int d_GSLOT[3] = {0, 3, 5};

// ---------------------------------------------------------------------------
// Kernel 1: channel-chunk reduction.  grid = (NCHUNK, B), block = 196.
// ~8 TB/s effective — at the HBM/LTS cap.  PDL trigger after partial stores.
// ---------------------------------------------------------------------------
__global__ void __launch_bounds__(196) appm_reduce_kernel(const float* __restrict__ x)
{
    const int chunk = blockIdx.x;
    const int b     = blockIdx.y;
    const int t     = threadIdx.x;
    const int q     = t % 49;
    const int cw    = t / 49;

    const float4* base = reinterpret_cast<const float4*>(x)
                       + ((size_t)b * C + (size_t)chunk * CCHUNK) * 49;

    float4 acc = make_float4(0.f, 0.f, 0.f, 0.f);
#pragma unroll 8
    for (int c = cw; c < CCHUNK; c += 4) {
        float4 v = __ldcs(base + (size_t)c * 49 + q);
        acc.x += v.x; acc.y += v.y; acc.z += v.z; acc.w += v.w;
    }

    __shared__ float s[NPIX];
    if (t < NPIX) s[t] = 0.f;
    __syncthreads();
    atomicAdd(&s[q * 4 + 0], acc.x);
    atomicAdd(&s[q * 4 + 1], acc.y);
    atomicAdd(&s[q * 4 + 2], acc.z);
    atomicAdd(&s[q * 4 + 3], acc.w);
    __syncthreads();
    if (t < NPIX)
        g_partial[(chunk * B + b) * NPIX + t] = s[t];
    __syncthreads();
    cudaTriggerProgrammaticLaunchCompletion();   // partials stored
}

// ---------------------------------------------------------------------------
// Kernel 2: per-(batch, group) scores + greedy NMS.  grid = (B, 3), block 256.
// PDL-launched.  Data-independent prologue (coords, meta, valid, SAT borders)
// runs BEFORE cudaGridDependencySynchronize(), hidden under k1's tail.
// Output layout (fp32): [B*6 indices][B*6 scores][B*837 all_scores]
// ---------------------------------------------------------------------------
__global__ void __launch_bounds__(256) appm_nms_kernel(float* __restrict__ out)
{
    const int b   = blockIdx.x;
    const int g   = blockIdx.y;
    const int tid = threadIdx.x;
    const int lane = tid & 31;
    const int wid  = tid >> 5;

    const int goff  = d_GOFF[g];
    const int W     = d_GW[g];
    const int nsel  = d_GN[g];
    const int slot0 = d_GSLOT[g];
    const int r0    = d_GR0[g];

    __shared__ float  y[NPIX];
    __shared__ float  SAT[FM + 1][FM + 1];
    __shared__ float  sc[361];
    __shared__ float  cx0[361], cy0[361], cx1[361], cy1[361];
    __shared__ int    wmeta[361];                 // i | j<<8 | rh<<16 | rw<<24
    __shared__ unsigned char valid[361];
    __shared__ float  warp_s[8];
    __shared__ int    warp_i[8];
    __shared__ int    sel_sh;
    __shared__ int    anyv_sh;

    // ======= data-independent prologue (overlaps k1 tail via PDL) =======
    if (tid < FM + 1) { SAT[0][tid] = 0.f; SAT[tid][0] = 0.f; }
    for (int w = tid; w < W; w += 256) {
        const int gw = goff + w;
        int r = r0;
        while (gw >= d_WOFF[r + 1]) r++;
        const int loc = gw - d_WOFF[r];
        const int rh  = d_RH[r], rw = d_RW[r];
        const int nw  = FM - rw + 1;
        const int i   = loc / nw, j = loc % nw;
        wmeta[w] = i | (j << 8) | (rh << 16) | (rw << 24);
        cx0[w] = (float)(j * 32);
        cy0[w] = (float)(i * 32);
        cx1[w] = (float)((j + rw) * 32 - 1);
        cy1[w] = (float)((i + rh) * 32 - 1);
        valid[w] = 1;
    }

    cudaGridDependencySynchronize();              // k1 partials now visible

    // ======= data-dependent phase =======
    if (tid < NPIX) {
        float acc = 0.f;
#pragma unroll
        for (int ch = 0; ch < NCHUNK; ch++)
            acc += g_partial[(ch * B + b) * NPIX + tid];
        y[tid] = acc;
    }
    __syncthreads();

    // integral image in float (FADD lat-4 chains; matches ref to ~2.5e-7)
    if (tid < FM) {
        float r = 0.f;
#pragma unroll
        for (int j = 0; j < FM; j++) {
            r += y[tid * FM + j];
            SAT[tid + 1][j + 1] = r;
        }
    }
    __syncthreads();
    if (tid < FM) {
        float r = 0.f;
#pragma unroll
        for (int i = 1; i <= FM; i++) {
            r += SAT[i][tid + 1];
            SAT[i][tid + 1] = r;
        }
    }
    __syncthreads();

    // window scores from packed meta
    for (int w = tid; w < W; w += 256) {
        const int m  = wmeta[w];
        const int i  = m & 255, j = (m >> 8) & 255;
        const int rh = (m >> 16) & 255, rw = (m >> 24) & 255;
        const float s = SAT[i + rh][j + rw] - SAT[i][j + rw]
                      - SAT[i + rh][j]      + SAT[i][j];
        const float sv = s / (float)(rh * rw);
        sc[w] = sv;
        out[2 * B * 6 + (size_t)b * TW + goff + w] = sv;   // all_scores
    }
    __syncthreads();

    // ---- greedy NMS for this group ----
    int last = 0;
    for (int step = 0; step < nsel; step++) {
        float bs = -CUDART_INF_F;
        int   bi = 0x7fffffff;
        for (int w = tid; w < W; w += 256) {
            if (valid[w]) {
                const float s = sc[w];
                if (s > bs) { bs = s; bi = w; }   // first max kept = jnp.argmax
            }
        }
#pragma unroll
        for (int o = 16; o > 0; o >>= 1) {
            const float s2 = __shfl_down_sync(0xffffffffu, bs, o);
            const int   i2 = __shfl_down_sync(0xffffffffu, bi, o);
            if (s2 > bs || (s2 == bs && i2 < bi)) { bs = s2; bi = i2; }
        }
        if (lane == 0) { warp_s[wid] = bs; warp_i[wid] = bi; }
        __syncthreads();
        if (tid == 0) {
            float fs = warp_s[0]; int fi = warp_i[0];
#pragma unroll
            for (int k = 1; k < 8; k++) {
                const float s2 = warp_s[k]; const int i2 = warp_i[k];
                if (s2 > fs || (s2 == fs && i2 < fi)) { fs = s2; fi = i2; }
            }
            const bool anyv = fs > -CUDART_INF_F;
            anyv_sh = anyv ? 1 : 0;
            sel_sh  = anyv ? fi : last;          // fallback: repeat last
        }
        __syncthreads();
        const int idx = sel_sh;
        if (tid == 0)
            out[(size_t)b * 6 + slot0 + step] = (float)(goff + idx);
        if (tid == 1)
            out[B * 6 + (size_t)b * 6 + slot0 + step] = sc[idx];

        if (anyv_sh) {
            const float sx0 = cx0[idx], sy0 = cy0[idx];
            const float sx1 = cx1[idx], sy1 = cy1[idx];
            const float sarea = (sx1 - sx0 + 1.f) * (sy1 - sy0 + 1.f);
            for (int w = tid; w < W; w += 256) {
                const float lx = fmaxf(cx0[w], sx0);
                const float ly = fmaxf(cy0[w], sy0);
                const float rx = fminf(cx1[w], sx1);
                const float ry = fminf(cy1[w], sy1);
                const float wx = rx - lx + 1.f;
                const float wy = ry - ly + 1.f;
                const float inter = (wx < 0.f || wy < 0.f) ? 0.f : wx * wy;
                const float area  = (cx1[w] - cx0[w] + 1.f) * (cy1[w] - cy0[w] + 1.f);
                const float iou   = inter / (area + sarea - inter);
                if (iou > 0.25f) valid[w] = 0;   // self-IoU=1 clears sel
            }
            if (tid == 0) valid[idx] = 0;
        }
        last = idx;
        __syncthreads();
    }
}

extern "C" void kernel_launch(void* const* d_in, const int* in_sizes, int n_in,
                              void* d_out, int out_size)
{
    const float* x = (const float*)d_in[0];
    float* out = (float*)d_out;

    appm_reduce_kernel<<<dim3(NCHUNK, B), 196>>>(x);

    cudaLaunchConfig_t cfg = {};
    cfg.gridDim  = dim3(B, 3);
    cfg.blockDim = dim3(256);
    cudaLaunchAttribute attrs[1];
    attrs[0].id = cudaLaunchAttributeProgrammaticStreamSerialization;
    attrs[0].val.programmaticStreamSerializationAllowed = 1;
    cfg.attrs    = attrs;
    cfg.numAttrs = 1;
    cudaLaunchKernelEx(&cfg, appm_nms_kernel, out);
}

// round 15
// speedup vs baseline: 1.3855x; 1.3735x over previous
#include <cuda_runtime.h>
#include <math_constants.h>

#define B      64
#define C      2048
#define FM     14
#define NPIX   196
#define NCHUNK 16
#define CCHUNK 128   // C / NCHUNK
#define TW     837

// scratch for per-chunk partial channel sums (no cudaMalloc allowed)
__device__ float g_partial[NCHUNK * B * NPIX];

__constant__ int d_RH[11]   = {4,3,5,6,5,7,8,6,10,7,9};
__constant__ int d_RW[11]   = {4,5,3,6,7,5,8,10,6,9,7};
__constant__ int d_WOFF[12] = {0,121,241,361,442,522,602,651,696,741,789,837};
__constant__ int d_GR0[3]   = {0, 3, 6};
__constant__ int d_GOFF[3]  = {0, 361, 602};
__constant__ int d_GW[3]    = {361, 241, 235};
__constant__ int d_GN[3]    = {3, 2, 1};
__constant__ int d_GSLOT[3] = {0, 3, 5};

// ---------------------------------------------------------------------------
// Kernel 1: channel-chunk reduction.  grid = (NCHUNK, B), block = 196.
// ~8 TB/s effective — at the HBM/LTS cap.  PDL trigger after partial stores.
// ---------------------------------------------------------------------------
__global__ void __launch_bounds__(196) appm_reduce_kernel(const float* __restrict__ x)
{
    const int chunk = blockIdx.x;
    const int b     = blockIdx.y;
    const int t     = threadIdx.x;
    const int q     = t % 49;
    const int cw    = t / 49;

    const float4* base = reinterpret_cast<const float4*>(x)
                       + ((size_t)b * C + (size_t)chunk * CCHUNK) * 49;

    float4 acc = make_float4(0.f, 0.f, 0.f, 0.f);
#pragma unroll 8
    for (int c = cw; c < CCHUNK; c += 4) {
        float4 v = __ldcs(base + (size_t)c * 49 + q);
        acc.x += v.x; acc.y += v.y; acc.z += v.z; acc.w += v.w;
    }

    __shared__ float s[NPIX];
    if (t < NPIX) s[t] = 0.f;
    __syncthreads();
    atomicAdd(&s[q * 4 + 0], acc.x);
    atomicAdd(&s[q * 4 + 1], acc.y);
    atomicAdd(&s[q * 4 + 2], acc.z);
    atomicAdd(&s[q * 4 + 3], acc.w);
    __syncthreads();
    if (t < NPIX)
        g_partial[(chunk * B + b) * NPIX + t] = s[t];
    __syncthreads();
    cudaTriggerProgrammaticLaunchCompletion();   // partials stored
}

// ---------------------------------------------------------------------------
// Kernel 2: per-(batch, group) scores + greedy NMS.  grid = (B, 3), block 256.
// PDL-launched.  Data-independent prologue runs BEFORE
// cudaGridDependencySynchronize(), hidden under k1's tail.
// NMS: 2 barriers/step (all threads fold the 8 warp winners identically).
// Output layout (fp32): [B*6 indices][B*6 scores][B*837 all_scores]
// ---------------------------------------------------------------------------
__global__ void __launch_bounds__(256) appm_nms_kernel(float* __restrict__ out)
{
    const int b   = blockIdx.x;
    const int g   = blockIdx.y;
    const int tid = threadIdx.x;
    const int lane = tid & 31;
    const int wid  = tid >> 5;

    const int goff  = d_GOFF[g];
    const int W     = d_GW[g];
    const int nsel  = d_GN[g];
    const int slot0 = d_GSLOT[g];
    const int r0    = d_GR0[g];

    __shared__ float  y[NPIX];
    __shared__ float  SAT[FM + 1][FM + 1];
    __shared__ float  sc[361];
    __shared__ float  cx0[361], cy0[361], cx1[361], cy1[361];
    __shared__ int    wmeta[361];                 // i | j<<8 | rh<<16 | rw<<24
    __shared__ unsigned char valid[361];
    __shared__ float  warp_s[8];
    __shared__ int    warp_i[8];

    // ======= data-independent prologue (overlaps k1 tail via PDL) =======
    if (tid < FM + 1) { SAT[0][tid] = 0.f; SAT[tid][0] = 0.f; }
    for (int w = tid; w < W; w += 256) {
        const int gw = goff + w;
        int r = r0;
        while (gw >= d_WOFF[r + 1]) r++;
        const int loc = gw - d_WOFF[r];
        const int rh  = d_RH[r], rw = d_RW[r];
        const int nw  = FM - rw + 1;
        const int i   = loc / nw, j = loc % nw;
        wmeta[w] = i | (j << 8) | (rh << 16) | (rw << 24);
        cx0[w] = (float)(j * 32);
        cy0[w] = (float)(i * 32);
        cx1[w] = (float)((j + rw) * 32 - 1);
        cy1[w] = (float)((i + rh) * 32 - 1);
        valid[w] = 1;
    }

    cudaGridDependencySynchronize();              // k1 partials now visible

    // ======= data-dependent phase =======
    if (tid < NPIX) {
        float acc = 0.f;
#pragma unroll
        for (int ch = 0; ch < NCHUNK; ch++)
            acc += g_partial[(ch * B + b) * NPIX + tid];
        y[tid] = acc;
    }
    __syncthreads();

    // integral image in float (FADD lat-4 chains; matches ref to ~2.5e-7)
    if (tid < FM) {
        float r = 0.f;
#pragma unroll
        for (int j = 0; j < FM; j++) {
            r += y[tid * FM + j];
            SAT[tid + 1][j + 1] = r;
        }
    }
    __syncthreads();
    if (tid < FM) {
        float r = 0.f;
#pragma unroll
        for (int i = 1; i <= FM; i++) {
            r += SAT[i][tid + 1];
            SAT[i][tid + 1] = r;
        }
    }
    __syncthreads();

    // window scores from packed meta
    for (int w = tid; w < W; w += 256) {
        const int m  = wmeta[w];
        const int i  = m & 255, j = (m >> 8) & 255;
        const int rh = (m >> 16) & 255, rw = (m >> 24) & 255;
        const float s = SAT[i + rh][j + rw] - SAT[i][j + rw]
                      - SAT[i + rh][j]      + SAT[i][j];
        const float sv = s / (float)(rh * rw);
        sc[w] = sv;
        out[2 * B * 6 + (size_t)b * TW + goff + w] = sv;   // all_scores
    }
    __syncthreads();

    // ---- greedy NMS: 2 barriers/step ----
    int last = 0;
    for (int step = 0; step < nsel; step++) {
        float bs = -CUDART_INF_F;
        int   bi = 0x7fffffff;
        for (int w = tid; w < W; w += 256) {
            if (valid[w]) {
                const float s = sc[w];
                if (s > bs) { bs = s; bi = w; }   // first max kept = jnp.argmax
            }
        }
#pragma unroll
        for (int o = 16; o > 0; o >>= 1) {
            const float s2 = __shfl_down_sync(0xffffffffu, bs, o);
            const int   i2 = __shfl_down_sync(0xffffffffu, bi, o);
            if (s2 > bs || (s2 == bs && i2 < bi)) { bs = s2; bi = i2; }
        }
        if (lane == 0) { warp_s[wid] = bs; warp_i[wid] = bi; }
        __syncthreads();
        // every thread folds the 8 winners identically (no tid0 round-trip)
        float fs = warp_s[0]; int fi = warp_i[0];
#pragma unroll
        for (int k = 1; k < 8; k++) {
            const float s2 = warp_s[k]; const int i2 = warp_i[k];
            if (s2 > fs || (s2 == fs && i2 < fi)) { fs = s2; fi = i2; }
        }
        const bool anyv = fs > -CUDART_INF_F;
        const int  idx  = anyv ? fi : last;       // fallback: repeat last

        if (tid == 0)
            out[(size_t)b * 6 + slot0 + step] = (float)(goff + idx);
        if (tid == 1)
            out[B * 6 + (size_t)b * 6 + slot0 + step] = sc[idx];

        if (anyv) {
            const float sx0 = cx0[idx], sy0 = cy0[idx];
            const float sx1 = cx1[idx], sy1 = cy1[idx];
            const float sarea = (sx1 - sx0 + 1.f) * (sy1 - sy0 + 1.f);
            for (int w = tid; w < W; w += 256) {
                const float lx = fmaxf(cx0[w], sx0);
                const float ly = fmaxf(cy0[w], sy0);
                const float rx = fminf(cx1[w], sx1);
                const float ry = fminf(cy1[w], sy1);
                const float wx = rx - lx + 1.f;
                const float wy = ry - ly + 1.f;
                const float inter = (wx < 0.f || wy < 0.f) ? 0.f : wx * wy;
                const float area  = (cx1[w] - cx0[w] + 1.f) * (cy1[w] - cy0[w] + 1.f);
                const float iou   = inter / (area + sarea - inter);
                if (iou > 0.25f) valid[w] = 0;    // self-IoU=1 clears sel
            }
            if (tid == 0) valid[idx] = 0;
        }
        last = idx;
        __syncthreads();
    }
}

extern "C" void kernel_launch(void* const* d_in, const int* in_sizes, int n_in,
                              void* d_out, int out_size)
{
    const float* x = (const float*)d_in[0];
    float* out = (float*)d_out;

    appm_reduce_kernel<<<dim3(NCHUNK, B), 196>>>(x);

    cudaLaunchConfig_t cfg = {};
    cfg.gridDim  = dim3(B, 3);
    cfg.blockDim = dim3(256);
    cudaLaunchAttribute attrs[1];
    attrs[0].id = cudaLaunchAttributeProgrammaticStreamSerialization;
    attrs[0].val.programmaticStreamSerializationAllowed = 1;
    cfg.attrs    = attrs;
    cfg.numAttrs = 1;
    cudaLaunchKernelEx(&cfg, appm_nms_kernel, out);
}